// round 4
// baseline (speedup 1.0000x reference)
#include <cuda_runtime.h>

// DRNN: two stacked SimpleRNN(tanh) layers, persistent per-CTA kernel.
// B=512 rows, T=512 steps, D=64, H=100.
// 128 CTAs x 4 rows; 256 threads: warps 0-3 = layer1, warps 4-7 = layer2
// (software pipeline: layer2 computes step t-1 while layer1 computes step t).
// Weights live in REGISTERS (one output-unit column per thread), activations
// flow through double-buffered shared memory. Inner product uses packed
// fma.rn.f32x2 (2 MACs/instr) along the reduction dimension.

#define TT   512
#define BB   512
#define DD   64
#define HH   100
#define ROWS 4
#define HS   104   // padded row stride for h buffers (multiple of 4 floats)

__device__ __forceinline__ void ffma2(unsigned long long &acc,
                                      unsigned long long a,
                                      unsigned long long b) {
    asm("fma.rn.f32x2 %0, %1, %2, %0;" : "+l"(acc) : "l"(a), "l"(b));
}

__device__ __forceinline__ unsigned long long pack2(float lo, float hi) {
    unsigned long long r;
    asm("mov.b64 %0, {%1, %2};" : "=l"(r) : "f"(lo), "f"(hi));
    return r;
}

__device__ __forceinline__ float2 unpack2(unsigned long long v) {
    float2 r;
    asm("mov.b64 {%0, %1}, %2;" : "=f"(r.x), "=f"(r.y) : "l"(v));
    return r;
}

// Accurate tanh via exp (immune to -use_fast_math tanhf substitution).
__device__ __forceinline__ float tanh_f(float x) {
    float ax = fabsf(x);
    float e  = __expf(-2.0f * ax);          // in (0,1]
    float r  = (1.0f - e) / (1.0f + e);
    return copysignf(r, x);
}

// Accumulate 4 rows' dot products: acc_r += act_r[k] * w[k], k packed in pairs.
// NQ float4-chunks per row, weights taken from register array w at offset WOFF.
template<int NQ, int WOFF>
__device__ __forceinline__ void accum4(unsigned long long &acc0, unsigned long long &acc1,
                                       unsigned long long &acc2, unsigned long long &acc3,
                                       const float* r0p, const float* r1p,
                                       const float* r2p, const float* r3p,
                                       const unsigned long long (&w)[100])
{
    const ulonglong2* a0 = reinterpret_cast<const ulonglong2*>(r0p);
    const ulonglong2* a1 = reinterpret_cast<const ulonglong2*>(r1p);
    const ulonglong2* a2 = reinterpret_cast<const ulonglong2*>(r2p);
    const ulonglong2* a3 = reinterpret_cast<const ulonglong2*>(r3p);
    #pragma unroll
    for (int q = 0; q < NQ; ++q) {
        ulonglong2 v0 = a0[q], v1 = a1[q], v2 = a2[q], v3 = a3[q];
        unsigned long long wA = w[WOFF + 2*q];
        unsigned long long wB = w[WOFF + 2*q + 1];
        ffma2(acc0, v0.x, wA); ffma2(acc1, v1.x, wA);
        ffma2(acc2, v2.x, wA); ffma2(acc3, v3.x, wA);
        ffma2(acc0, v0.y, wB); ffma2(acc1, v1.y, wB);
        ffma2(acc2, v2.y, wB); ffma2(acc3, v3.y, wB);
    }
}

__global__ __launch_bounds__(256, 1)
void drnn_kernel(const float* __restrict__ X,
                 const float* __restrict__ W1x, const float* __restrict__ W1h,
                 const float* __restrict__ B1,
                 const float* __restrict__ W2x, const float* __restrict__ W2h,
                 const float* __restrict__ B2,
                 const float* __restrict__ Wo,  const float* __restrict__ Bo,
                 float* __restrict__ out)
{
    __shared__ __align__(16) float sX [2][ROWS][DD];
    __shared__ __align__(16) float sH1[2][ROWS][HS];
    __shared__ __align__(16) float sH2[2][ROWS][HS];

    const int tid = threadIdx.x;
    const int g   = tid >> 7;        // 0: layer1 warps, 1: layer2 warps
    const int lt  = tid & 127;
    const int j   = lt;              // output unit owned by this thread
    const bool active = (j < HH);
    const int r0 = blockIdx.x * ROWS;

    // Weight registers (union: layer1 uses [0..81], layer2 uses [0..99]).
    unsigned long long w[100];
    float bj = 0.f;

    if (g == 0) {
        if (active) {
            #pragma unroll
            for (int kp = 0; kp < DD/2; ++kp)              // W1x column j (64 vals)
                w[kp] = pack2(W1x[(2*kp)*HH + j], W1x[(2*kp+1)*HH + j]);
            #pragma unroll
            for (int kp = 0; kp < HH/2; ++kp)              // W1h column j (100 vals)
                w[32 + kp] = pack2(W1h[(2*kp)*HH + j], W1h[(2*kp+1)*HH + j]);
            bj = B1[j];
        }
    } else {
        if (active) {
            #pragma unroll
            for (int kp = 0; kp < HH/2; ++kp)              // W2x column j
                w[kp] = pack2(W2x[(2*kp)*HH + j], W2x[(2*kp+1)*HH + j]);
            #pragma unroll
            for (int kp = 0; kp < HH/2; ++kp)              // W2h column j
                w[50 + kp] = pack2(W2h[(2*kp)*HH + j], W2h[(2*kp+1)*HH + j]);
            bj = B2[j];
        }
    }

    // Zero state buffers (h_{-1} = 0) and stage x_0.
    for (int idx = tid; idx < 2*ROWS*HS; idx += 256) {
        (&sH1[0][0][0])[idx] = 0.f;
        (&sH2[0][0][0])[idx] = 0.f;
    }
    {
        int r = tid >> 6, d = tid & 63;                    // 256 threads = 4 rows x 64
        sX[0][r][d] = X[(size_t)(r0 + r)*TT*DD + d];
    }
    __syncthreads();

    for (int i = 0; i <= TT; ++i) {
        if (g == 0) {
            // Prefetch x_{i+1} (2 values per thread: 128 thr x 2 = 4 rows x 64).
            float xa = 0.f, xb = 0.f;
            const int rr = lt >> 6, d = lt & 63;
            if (i + 1 < TT) {
                xa = X[(size_t)(r0 + rr    )*TT*DD + (i+1)*DD + d];
                xb = X[(size_t)(r0 + 2 + rr)*TT*DD + (i+1)*DD + d];
            }
            if (i < TT && active) {
                const int pc = i & 1, pp = pc ^ 1;
                unsigned long long acc0=0, acc1=0, acc2=0, acc3=0;
                accum4<DD/4, 0 >(acc0, acc1, acc2, acc3,
                                 sX[pc][0],  sX[pc][1],  sX[pc][2],  sX[pc][3],  w);
                accum4<HH/4, 32>(acc0, acc1, acc2, acc3,
                                 sH1[pp][0], sH1[pp][1], sH1[pp][2], sH1[pp][3], w);
                float2 f0 = unpack2(acc0), f1 = unpack2(acc1);
                float2 f2 = unpack2(acc2), f3 = unpack2(acc3);
                sH1[pc][0][j] = tanh_f(f0.x + f0.y + bj);
                sH1[pc][1][j] = tanh_f(f1.x + f1.y + bj);
                sH1[pc][2][j] = tanh_f(f2.x + f2.y + bj);
                sH1[pc][3][j] = tanh_f(f3.x + f3.y + bj);
            }
            if (i + 1 < TT) {
                const int pn = (i + 1) & 1;
                sX[pn][rr    ][d] = xa;
                sX[pn][2 + rr][d] = xb;
            }
        } else {
            if (i >= 1 && active) {
                const int s  = i - 1;
                const int pc = s & 1, pp = pc ^ 1;
                unsigned long long acc0=0, acc1=0, acc2=0, acc3=0;
                accum4<HH/4, 0 >(acc0, acc1, acc2, acc3,
                                 sH1[pc][0], sH1[pc][1], sH1[pc][2], sH1[pc][3], w);
                accum4<HH/4, 50>(acc0, acc1, acc2, acc3,
                                 sH2[pp][0], sH2[pp][1], sH2[pp][2], sH2[pp][3], w);
                float2 f0 = unpack2(acc0), f1 = unpack2(acc1);
                float2 f2 = unpack2(acc2), f3 = unpack2(acc3);
                sH2[pc][0][j] = tanh_f(f0.x + f0.y + bj);
                sH2[pc][1][j] = tanh_f(f1.x + f1.y + bj);
                sH2[pc][2][j] = tanh_f(f2.x + f2.y + bj);
                sH2[pc][3][j] = tanh_f(f3.x + f3.y + bj);
            }
        }
        __syncthreads();
    }

    // Final states live at parity (TT-1)&1 == 1.
    float* outVec = out;                      // [512]
    float* outH1  = out + BB;                 // [512,100]
    float* outH2  = out + BB + BB*HH;         // [512,100]

    if (g == 0 && active) {
        #pragma unroll
        for (int r = 0; r < ROWS; ++r)
            outH1[(size_t)(r0 + r)*HH + j] = sH1[1][r][j];
    } else if (g == 1 && active) {
        #pragma unroll
        for (int r = 0; r < ROWS; ++r)
            outH2[(size_t)(r0 + r)*HH + j] = sH2[1][r][j];
    }

    // Output head: out[r] = h2_T[r] . Wo + bo  (warp 0 does all 4 rows)
    if (tid < 32) {
        #pragma unroll
        for (int r = 0; r < ROWS; ++r) {
            float v = 0.f;
            #pragma unroll
            for (int m = 0; m < 4; ++m) {
                int jj = m*32 + tid;
                if (jj < HH) v += sH2[1][r][jj] * Wo[jj];
            }
            #pragma unroll
            for (int off = 16; off; off >>= 1)
                v += __shfl_down_sync(0xffffffffu, v, off);
            if (tid == 0) outVec[r0 + r] = v + Bo[0];
        }
    }
}

extern "C" void kernel_launch(void* const* d_in, const int* in_sizes, int n_in,
                              void* d_out, int out_size) {
    (void)in_sizes; (void)n_in; (void)out_size;
    const float* X   = (const float*)d_in[0];
    const float* W1x = (const float*)d_in[1];
    const float* W1h = (const float*)d_in[2];
    const float* B1  = (const float*)d_in[3];
    const float* W2x = (const float*)d_in[4];
    const float* W2h = (const float*)d_in[5];
    const float* B2  = (const float*)d_in[6];
    const float* Wo  = (const float*)d_in[7];
    const float* Bo  = (const float*)d_in[8];
    drnn_kernel<<<BB/ROWS, 256>>>(X, W1x, W1h, B1, W2x, W2h, B2, Wo, Bo,
                                  (float*)d_out);
}